// round 1
// baseline (speedup 1.0000x reference)
#include <cuda_runtime.h>

// ---------------------------------------------------------------------------
// TimemixingFC_channel: two window-attention branches.
//   Per branch: qkv = x@Wfc^T + b  (96 -> 288)
//   Window attn with S=2 degenerates to: G = sum_m k_m (2) outer v_m (2)  [2x2]
//                                        o_m = q_m @ G
//   out = o @ Wp^T + bp
// Branch 2 == Branch 1 with temporal pairing shifted by -1 (rolls cancel into
// the pairing; every token's output stays at its own (b,d,h,w)).
// ---------------------------------------------------------------------------

#define SMEM_FLOATS 49280
#define SMEM_BYTES  (SMEM_FLOATS * 4)

// scratch: inter-branch intermediate + pre-transposed weights
__device__ float g_mid[2 * 16 * 32 * 32 * 96];   // 12.6 MB
__device__ float g_wT [2][3 * 96 * 96];          // [branch][comp][c][j] = Wfc[comp*96+j][c]
__device__ float g_wTp[2][96 * 96];              // [branch][c][j]       = Wp[j][c]

// ---------------------------------------------------------------------------
// Prep: transpose weights once so main blocks stage SMEM with clean float4.
// total elements = 2*(27648 + 9216) = 73728 -> grid 288 x 256 exactly.
// ---------------------------------------------------------------------------
__global__ void prep_kernel(const float* __restrict__ lr,
                            const float* __restrict__ pr,
                            const float* __restrict__ sw,
                            const float* __restrict__ prs)
{
    int idx = blockIdx.x * blockDim.x + threadIdx.x;
    const int FC = 3 * 96 * 96, PJ = 96 * 96;
    if (idx < FC) {
        int jf = idx / 96, c = idx % 96;
        g_wT[0][(jf / 96) * 9216 + c * 96 + (jf % 96)] = lr[idx];
        return;
    }
    idx -= FC;
    if (idx < PJ) {
        int j = idx / 96, c = idx % 96;
        g_wTp[0][c * 96 + j] = pr[idx];
        return;
    }
    idx -= PJ;
    if (idx < FC) {
        int jf = idx / 96, c = idx % 96;
        g_wT[1][(jf / 96) * 9216 + c * 96 + (jf % 96)] = sw[idx];
        return;
    }
    idx -= FC;
    if (idx < PJ) {
        int j = idx / 96, c = idx % 96;
        g_wTp[1][c * 96 + j] = prs[idx];
    }
}

// ---------------------------------------------------------------------------
// Register-tiled sub-GEMM: 256 thr as 16 row-groups x 16 col-groups.
// Each thread: 8 tokens x 6 output cols, K=96. A broadcast-friendly from smem,
// B conflict-free ([c][j], row stride 100).
// ---------------------------------------------------------------------------
__device__ __forceinline__ void gemm_tile(const float* __restrict__ As, int astride,
                                          const float* __restrict__ Ws,
                                          const float* __restrict__ bias,
                                          int r0, int j0, float acc[8][6])
{
    float bb[6];
#pragma unroll
    for (int jj = 0; jj < 6; jj++) bb[jj] = bias[j0 + jj];
#pragma unroll
    for (int rr = 0; rr < 8; rr++)
#pragma unroll
        for (int jj = 0; jj < 6; jj++) acc[rr][jj] = bb[jj];

    const float* a0 = As + r0 * astride;
#pragma unroll 4
    for (int c = 0; c < 96; c++) {
        float a[8];
#pragma unroll
        for (int rr = 0; rr < 8; rr++) a[rr] = a0[rr * astride + c];
        float b[6];
        const float* wr = Ws + c * 100 + j0;
#pragma unroll
        for (int jj = 0; jj < 6; jj++) b[jj] = wr[jj];
#pragma unroll
        for (int rr = 0; rr < 8; rr++)
#pragma unroll
            for (int jj = 0; jj < 6; jj++)
                acc[rr][jj] = fmaf(a[rr], b[jj], acc[rr][jj]);
    }
}

// ---------------------------------------------------------------------------
// Fused branch kernel. Block = (b, dw, 64 spatial positions) -> 128 tokens
// (64 positions x 2 temporal frames d0,d1). Grid = 2*8*16 = 256 blocks.
// ---------------------------------------------------------------------------
__global__ void __launch_bounds__(256)
fused_branch(const float* __restrict__ xin_ext,
             const float* __restrict__ qkv_b,
             const float* __restrict__ pr_b,
             float* __restrict__ out_ext,
             int branch, int shift)
{
    extern __shared__ float sm[];
    float* xs = sm;             // 128 x 96   (tokens, natural layout)
    float* ws = sm + 12288;     // 96 x 100   (weights, [c][j] padded)
    float* kb = sm + 21888;     // 128 x 104  (k, then q)
    float* vb = sm + 35200;     // 128 x 104  (v, then o)
    float* gt = sm + 48512;     // 128 x 4    per-token G partials
    float* gc = sm + 49024;     // 64 x 4     per-group combined G

    const float* X  = branch ? g_mid : xin_ext;
    float*       O  = branch ? out_ext : g_mid;
    const float* WQ = g_wT[branch];
    const float* WP = g_wTp[branch];

    int tid   = threadIdx.x;
    int chunk = blockIdx.x & 15;
    int bdw   = blockIdx.x >> 4;
    int b     = bdw >> 3, dw = bdw & 7;
    int d0    = (2 * dw + shift) & 15;
    int d1    = (2 * dw + 1 + shift) & 15;
    int pbase = chunk * 64;

    int base0 = ((b * 16 + d0) * 1024 + pbase) * 96;
    int base1 = ((b * 16 + d1) * 1024 + pbase) * 96;

    // ---- stage x: 128 tokens x 96 ch, float4 ----
    for (int f4 = tid; f4 < 3072; f4 += 256) {
        int l = f4 / 24, q = (f4 % 24) * 4;
        int g = (l < 64 ? base0 + l * 96 : base1 + (l - 64) * 96) + q;
        *(float4*)&xs[l * 96 + q] = *(const float4*)&X[g];
    }

    int cgrp = tid & 15, rgrp = tid >> 4;
    int r0 = rgrp * 8, j0 = cgrp * 6;
    float acc[8][6];

    // ---- K component ----
    for (int f4 = tid; f4 < 2304; f4 += 256) {
        int c = f4 / 24, q = (f4 % 24) * 4;
        *(float4*)&ws[c * 100 + q] = *(const float4*)&WQ[9216 + c * 96 + q];
    }
    __syncthreads();
    gemm_tile(xs, 96, ws, qkv_b + 96, r0, j0, acc);
#pragma unroll
    for (int rr = 0; rr < 8; rr++)
#pragma unroll
        for (int jj = 0; jj < 6; jj++)
            kb[(r0 + rr) * 104 + j0 + jj] = acc[rr][jj];
    __syncthreads();

    // ---- V component ----
    for (int f4 = tid; f4 < 2304; f4 += 256) {
        int c = f4 / 24, q = (f4 % 24) * 4;
        *(float4*)&ws[c * 100 + q] = *(const float4*)&WQ[2 * 9216 + c * 96 + q];
    }
    __syncthreads();
    gemm_tile(xs, 96, ws, qkv_b + 192, r0, j0, acc);
#pragma unroll
    for (int rr = 0; rr < 8; rr++)
#pragma unroll
        for (int jj = 0; jj < 6; jj++)
            vb[(r0 + rr) * 104 + j0 + jj] = acc[rr][jj];
    __syncthreads();

    // ---- preload Q weights (ws free) + compute 2x2 G per token, then per group
    for (int f4 = tid; f4 < 2304; f4 += 256) {
        int c = f4 / 24, q = (f4 % 24) * 4;
        *(float4*)&ws[c * 100 + q] = *(const float4*)&WQ[c * 96 + q];
    }
    {
        int l = tid >> 1, h = tid & 1;         // 2 threads per token
        const float4* k4p = (const float4*)kb; // row stride 26 float4
        const float4* v4p = (const float4*)vb;
        float g00 = 0, g01 = 0, g10 = 0, g11 = 0;
        int base = l * 26 + h * 12;
#pragma unroll
        for (int s = 0; s < 12; s++) {
            float4 k4 = k4p[base + s];
            float4 v4 = v4p[base + s];
            g00 = fmaf(k4.x, v4.x, fmaf(k4.z, v4.z, g00));
            g01 = fmaf(k4.x, v4.y, fmaf(k4.z, v4.w, g01));
            g10 = fmaf(k4.y, v4.x, fmaf(k4.w, v4.z, g10));
            g11 = fmaf(k4.y, v4.y, fmaf(k4.w, v4.w, g11));
        }
        if (h == 1) {
            gt[l * 4] = g00; gt[l * 4 + 1] = g01;
            gt[l * 4 + 2] = g10; gt[l * 4 + 3] = g11;
        }
        __syncthreads();
        if (h == 0) {
            gt[l * 4]     += g00; gt[l * 4 + 1] += g01;
            gt[l * 4 + 2] += g10; gt[l * 4 + 3] += g11;
        }
        __syncthreads();
        if (tid < 64) {
#pragma unroll
            for (int k = 0; k < 4; k++)
                gc[tid * 4 + k] = gt[tid * 4 + k] + gt[(tid + 64) * 4 + k];
        }
    }
    __syncthreads();

    // ---- Q component -> kb ----
    gemm_tile(xs, 96, ws, qkv_b, r0, j0, acc);
#pragma unroll
    for (int rr = 0; rr < 8; rr++)
#pragma unroll
        for (int jj = 0; jj < 6; jj++)
            kb[(r0 + rr) * 104 + j0 + jj] = acc[rr][jj];
    __syncthreads();

    // ---- preload proj weights + o = q @ G (into vb) ----
    for (int f4 = tid; f4 < 2304; f4 += 256) {
        int c = f4 / 24, q = (f4 % 24) * 4;
        *(float4*)&ws[c * 100 + q] = *(const float4*)&WP[c * 96 + q];
    }
    {
        const float4* k4p = (const float4*)kb;
        float4*       v4p = (float4*)vb;
        for (int f4 = tid; f4 < 3072; f4 += 256) {
            int l = f4 / 24, s = f4 % 24;
            int pi = l & 63;
            float G00 = gc[pi * 4], G01 = gc[pi * 4 + 1];
            float G10 = gc[pi * 4 + 2], G11 = gc[pi * 4 + 3];
            float4 q4 = k4p[l * 26 + s];
            float4 o4;
            o4.x = q4.x * G00 + q4.y * G10;
            o4.y = q4.x * G01 + q4.y * G11;
            o4.z = q4.z * G00 + q4.w * G10;
            o4.w = q4.z * G01 + q4.w * G11;
            v4p[l * 26 + s] = o4;
        }
    }
    __syncthreads();

    // ---- proj GEMM from o (vb, stride 104) -> gmem ----
    gemm_tile(vb, 104, ws, pr_b, r0, j0, acc);
#pragma unroll
    for (int rr = 0; rr < 8; rr++) {
        int l = r0 + rr;
        int g = (l < 64 ? base0 + l * 96 : base1 + (l - 64) * 96) + j0;
#pragma unroll
        for (int jj = 0; jj < 6; jj += 2)
            *(float2*)&O[g + jj] = make_float2(acc[rr][jj], acc[rr][jj + 1]);
    }
}

// ---------------------------------------------------------------------------
extern "C" void kernel_launch(void* const* d_in, const int* in_sizes, int n_in,
                              void* d_out, int out_size)
{
    const float* x       = (const float*)d_in[0];
    const float* lr_w    = (const float*)d_in[1];
    const float* lr_b    = (const float*)d_in[2];
    const float* proj_w  = (const float*)d_in[3];
    const float* proj_b  = (const float*)d_in[4];
    const float* sw_w    = (const float*)d_in[5];
    const float* sw_b    = (const float*)d_in[6];
    const float* projs_w = (const float*)d_in[7];
    const float* projs_b = (const float*)d_in[8];
    float* out = (float*)d_out;

    // idempotent, not a stream op -> capture-safe
    cudaFuncSetAttribute(fused_branch,
                         cudaFuncAttributeMaxDynamicSharedMemorySize, SMEM_BYTES);

    prep_kernel<<<288, 256>>>(lr_w, proj_w, sw_w, projs_w);
    // branch 0: pairs (2w, 2w+1), x -> g_mid
    fused_branch<<<256, 256, SMEM_BYTES>>>(x, lr_b, proj_b, nullptr, 0, 0);
    // branch 1: pairs ((2w+15)&15, 2w) == rolls folded in, g_mid -> out
    fused_branch<<<256, 256, SMEM_BYTES>>>(nullptr, sw_b, projs_b, out, 1, 15);
}

// round 3
// speedup vs baseline: 1.1437x; 1.1437x over previous
#include <cuda_runtime.h>

// ---------------------------------------------------------------------------
// TimemixingFC_channel: two window-attention branches, algebraically reduced.
//   Per branch: qkv = x@Wfc^T + b (96 -> 288); S=2 attention degenerates to a
//   2x2 G = sum_seg k ⊗ v per (position, window) group; o = q @ G; proj.
//   Branch-0's proj is folded into branch-1's QKV:
//     W' = Wsw @ Wp,  b' = Wsw @ bp + bsw   (computed once in prep)
//   so the inter-branch intermediate is o0 (pre-proj). Temporal rolls cancel
//   into the frame pairing (shift), outputs stay at their own token.
// Grid = 296 = 2 exact waves of 148 SMs; blocks carry 55/56 position-groups.
// ---------------------------------------------------------------------------

#define SMEM_FLOATS 43536
#define SMEM_BYTES  (SMEM_FLOATS * 4)

__device__ float g_mid[2 * 16 * 32 * 32 * 96];   // o0 intermediate (pre-proj)
__device__ float g_wT [2][3 * 96 * 96];          // [branch][comp][c][j]; branch1 = W'
__device__ float g_wTp[96 * 96];                 // branch-1 FINAL proj (projs_w), [c][j]
__device__ float g_b1 [3 * 96];                  // b' = Wsw@bp + bsw

// ---------------------------------------------------------------------------
// Prep. Grid = 254 x 256.
//   blocks [0,108):   transpose lr_w    -> g_wT[0]
//   blocks [108,144): transpose projs_w -> g_wTp      (branch-1 final proj!)
//   blocks [144,252): W' = sw_w @ proj_w, transposed -> g_wT[1]
//   blocks [252,254): b' = sw_w @ proj_b + sw_b       -> g_b1
// ---------------------------------------------------------------------------
__global__ void prep_kernel(const float* __restrict__ lr,
                            const float* __restrict__ pr,    // proj_w  (fold)
                            const float* __restrict__ prs,   // projs_w (final proj)
                            const float* __restrict__ sw,
                            const float* __restrict__ swb,
                            const float* __restrict__ prb)   // proj_b  (fold)
{
    int bid = blockIdx.x, tid = threadIdx.x;
    if (bid < 108) {
        int idx = bid * 256 + tid;            // < 27648
        int jf = idx / 96, c = idx % 96;
        g_wT[0][(jf / 96) * 9216 + c * 96 + (jf % 96)] = lr[idx];
    } else if (bid < 144) {
        int idx = (bid - 108) * 256 + tid;    // < 9216
        int j = idx / 96, c = idx % 96;
        g_wTp[c * 96 + j] = prs[idx];
    } else if (bid < 252) {
        __shared__ float pws[9216];
        for (int i = tid; i < 9216; i += 256) pws[i] = pr[i];
        __syncthreads();
        int idx = (bid - 144) * 256 + tid;    // < 27648
        int jf = idx / 96, c = idx % 96;
        const float* swr = sw + jf * 96;
        float s = 0.f;
#pragma unroll 8
        for (int t = 0; t < 96; t++) s = fmaf(swr[t], pws[t * 96 + c], s);
        g_wT[1][(jf / 96) * 9216 + c * 96 + (jf % 96)] = s;
    } else {
        int r = (bid - 252) * 256 + tid;
        if (r < 288) {
            const float* swr = sw + r * 96;
            float s = swb[r];
#pragma unroll 8
            for (int t = 0; t < 96; t++) s = fmaf(swr[t], prb[t], s);
            g_b1[r] = s;
        }
    }
}

// ---------------------------------------------------------------------------
// Register-tiled sub-GEMM: 256 thr = 16 rgrp (7 rows) x 16 cgrp (6 cols).
// K = 96. A from smem (broadcast), B [c][j] stride 100 (conflict-free).
// ---------------------------------------------------------------------------
__device__ __forceinline__ void gemm_tile(const float* __restrict__ As, int astride,
                                          const float* __restrict__ Ws,
                                          const float* __restrict__ bias,
                                          int r0, int j0, float acc[7][6])
{
    float bb[6];
#pragma unroll
    for (int jj = 0; jj < 6; jj++) bb[jj] = bias[j0 + jj];
#pragma unroll
    for (int rr = 0; rr < 7; rr++)
#pragma unroll
        for (int jj = 0; jj < 6; jj++) acc[rr][jj] = bb[jj];

    const float* a0 = As + r0 * astride;
#pragma unroll 4
    for (int c = 0; c < 96; c++) {
        float a[7];
#pragma unroll
        for (int rr = 0; rr < 7; rr++) a[rr] = a0[rr * astride + c];
        float b[6];
        const float* wr = Ws + c * 100 + j0;
#pragma unroll
        for (int jj = 0; jj < 6; jj++) b[jj] = wr[jj];
#pragma unroll
        for (int rr = 0; rr < 7; rr++)
#pragma unroll
            for (int jj = 0; jj < 6; jj++)
                acc[rr][jj] = fmaf(a[rr], b[jj], acc[rr][jj]);
    }
}

// ---------------------------------------------------------------------------
// Fused branch kernel. Grid = 296 (2 exact waves). Block handles P (55/56)
// position-groups = 2P tokens (frames d0,d1 of each position).
// branch 0: x -> o0 (g_mid), 3 GEMM phases (K,V,Q) + G + direct o store.
// branch 1: o0 -> out,       3 GEMM phases + G + o + proj GEMM.
// ---------------------------------------------------------------------------
__global__ void __launch_bounds__(256)
fused_branch(const float* __restrict__ xin_ext,
             const float* __restrict__ qkv_b_ext,
             const float* __restrict__ pr_b,
             float* __restrict__ out_ext,
             int branch, int shift)
{
    extern __shared__ float sm[];
    float* xs = sm;              // 112 x 96
    float* ws = sm + 10752;      // 96 x 100
    float* kb = sm + 20352;      // 112 x 100  (k, then q)
    float* vb = sm + 31552;      // 112 x 100  (v, then o; branch1 only)
    float* gt = sm + 42752;      // 112 x 4
    float* gc = sm + 43200;      // 56 x 4
    int*   tb = (int*)(sm + 43424); // 112 token gmem bases

    const float* X  = branch ? g_mid : xin_ext;
    float*       O  = branch ? out_ext : g_mid;
    const float* WQ = g_wT[branch];
    const float* QB = branch ? g_b1 : qkv_b_ext;

    int tid = threadIdx.x, bid = blockIdx.x;
    int P, s;
    if (bid < 104) { P = 56; s = bid * 56; }
    else           { P = 55; s = 5824 + (bid - 104) * 55; }
    int T = 2 * P, F4 = T * 24;

    // token base addresses
    if (tid < T) {
        int pi = tid < P ? tid : tid - P;
        int g = s + pi;
        int b = g >> 13, dw = (g >> 10) & 7, p = g & 1023;
        int d = (2 * dw + (tid < P ? 0 : 1) + shift) & 15;
        tb[tid] = ((b * 16 + d) * 1024 + p) * 96;
    }
    __syncthreads();

    // stage x (zero-fill tail rows so tile A-reads are clean)
    for (int f4 = tid; f4 < 2688; f4 += 256) {
        int l = f4 / 24, q = (f4 % 24) * 4;
        float4 v = make_float4(0.f, 0.f, 0.f, 0.f);
        if (l < T) v = *(const float4*)&X[tb[l] + q];
        *(float4*)&xs[l * 96 + q] = v;
    }

    int cgrp = tid & 15, rgrp = tid >> 4;
    int r0 = rgrp * 7, j0 = cgrp * 6;
    float acc[7][6];

    // ---- K ----
    for (int f4 = tid; f4 < 2304; f4 += 256) {
        int c = f4 / 24, q = (f4 % 24) * 4;
        *(float4*)&ws[c * 100 + q] = *(const float4*)&WQ[9216 + c * 96 + q];
    }
    __syncthreads();
    gemm_tile(xs, 96, ws, QB + 96, r0, j0, acc);
#pragma unroll
    for (int rr = 0; rr < 7; rr++)
#pragma unroll
        for (int jj = 0; jj < 6; jj++)
            kb[(r0 + rr) * 100 + j0 + jj] = acc[rr][jj];
    __syncthreads();

    // ---- V ----
    for (int f4 = tid; f4 < 2304; f4 += 256) {
        int c = f4 / 24, q = (f4 % 24) * 4;
        *(float4*)&ws[c * 100 + q] = *(const float4*)&WQ[2 * 9216 + c * 96 + q];
    }
    __syncthreads();
    gemm_tile(xs, 96, ws, QB + 192, r0, j0, acc);
#pragma unroll
    for (int rr = 0; rr < 7; rr++)
#pragma unroll
        for (int jj = 0; jj < 6; jj++)
            vb[(r0 + rr) * 100 + j0 + jj] = acc[rr][jj];
    __syncthreads();

    // ---- stage Q weights + per-group 2x2 G ----
    for (int f4 = tid; f4 < 2304; f4 += 256) {
        int c = f4 / 24, q = (f4 % 24) * 4;
        *(float4*)&ws[c * 100 + q] = *(const float4*)&WQ[c * 96 + q];
    }
    {
        int l = tid >> 1, h = tid & 1;
        float g00 = 0, g01 = 0, g10 = 0, g11 = 0;
        if (l < T) {
            const float4* k4p = (const float4*)kb;   // row stride 25 f4
            const float4* v4p = (const float4*)vb;
            int base = l * 25 + h * 12;
#pragma unroll
            for (int ss = 0; ss < 12; ss++) {
                float4 k4 = k4p[base + ss];
                float4 v4 = v4p[base + ss];
                g00 = fmaf(k4.x, v4.x, fmaf(k4.z, v4.z, g00));
                g01 = fmaf(k4.x, v4.y, fmaf(k4.z, v4.w, g01));
                g10 = fmaf(k4.y, v4.x, fmaf(k4.w, v4.z, g10));
                g11 = fmaf(k4.y, v4.y, fmaf(k4.w, v4.w, g11));
            }
            if (h == 1) {
                gt[l * 4] = g00; gt[l * 4 + 1] = g01;
                gt[l * 4 + 2] = g10; gt[l * 4 + 3] = g11;
            }
        }
        __syncthreads();
        if (l < T && h == 0) {
            gt[l * 4]     += g00; gt[l * 4 + 1] += g01;
            gt[l * 4 + 2] += g10; gt[l * 4 + 3] += g11;
        }
        __syncthreads();
        if (tid < P) {
#pragma unroll
            for (int k = 0; k < 4; k++)
                gc[tid * 4 + k] = gt[tid * 4 + k] + gt[(tid + P) * 4 + k];
        }
    }
    __syncthreads();

    // ---- Q -> kb ----
    gemm_tile(xs, 96, ws, QB, r0, j0, acc);
#pragma unroll
    for (int rr = 0; rr < 7; rr++)
#pragma unroll
        for (int jj = 0; jj < 6; jj++)
            kb[(r0 + rr) * 100 + j0 + jj] = acc[rr][jj];
    __syncthreads();

    if (branch == 0) {
        // ---- o = q @ G, streamed straight to gmem (g_mid) ----
        const float4* k4p = (const float4*)kb;
        for (int f4 = tid; f4 < F4; f4 += 256) {
            int l = f4 / 24, sf = f4 % 24;
            int pi = l < P ? l : l - P;
            float G00 = gc[pi * 4], G01 = gc[pi * 4 + 1];
            float G10 = gc[pi * 4 + 2], G11 = gc[pi * 4 + 3];
            float4 q4 = k4p[l * 25 + sf];
            float4 o4;
            o4.x = q4.x * G00 + q4.y * G10;
            o4.y = q4.x * G01 + q4.y * G11;
            o4.z = q4.z * G00 + q4.w * G10;
            o4.w = q4.z * G01 + q4.w * G11;
            *(float4*)&O[tb[l] + sf * 4] = o4;
        }
    } else {
        // ---- stage FINAL proj weights (projs_w) + o = q @ G -> vb ----
        for (int f4 = tid; f4 < 2304; f4 += 256) {
            int c = f4 / 24, q = (f4 % 24) * 4;
            *(float4*)&ws[c * 100 + q] = *(const float4*)&g_wTp[c * 96 + q];
        }
        {
            const float4* k4p = (const float4*)kb;
            float4*       v4p = (float4*)vb;
            for (int f4 = tid; f4 < F4; f4 += 256) {
                int l = f4 / 24, sf = f4 % 24;
                int pi = l < P ? l : l - P;
                float G00 = gc[pi * 4], G01 = gc[pi * 4 + 1];
                float G10 = gc[pi * 4 + 2], G11 = gc[pi * 4 + 3];
                float4 q4 = k4p[l * 25 + sf];
                float4 o4;
                o4.x = q4.x * G00 + q4.y * G10;
                o4.y = q4.x * G01 + q4.y * G11;
                o4.z = q4.z * G00 + q4.w * G10;
                o4.w = q4.z * G01 + q4.w * G11;
                v4p[l * 25 + sf] = o4;
            }
        }
        __syncthreads();

        // ---- proj GEMM -> out ----
        gemm_tile(vb, 100, ws, pr_b, r0, j0, acc);
#pragma unroll
        for (int rr = 0; rr < 7; rr++) {
            int l = r0 + rr;
            if (l < T) {
                int g = tb[l] + j0;
#pragma unroll
                for (int jj = 0; jj < 6; jj += 2)
                    *(float2*)&O[g + jj] = make_float2(acc[rr][jj], acc[rr][jj + 1]);
            }
        }
    }
}

// ---------------------------------------------------------------------------
extern "C" void kernel_launch(void* const* d_in, const int* in_sizes, int n_in,
                              void* d_out, int out_size)
{
    const float* x       = (const float*)d_in[0];
    const float* lr_w    = (const float*)d_in[1];
    const float* lr_b    = (const float*)d_in[2];
    const float* proj_w  = (const float*)d_in[3];
    const float* proj_b  = (const float*)d_in[4];
    const float* sw_w    = (const float*)d_in[5];
    const float* sw_b    = (const float*)d_in[6];
    const float* projs_w = (const float*)d_in[7];
    const float* projs_b = (const float*)d_in[8];
    float* out = (float*)d_out;

    cudaFuncSetAttribute(fused_branch,
                         cudaFuncAttributeMaxDynamicSharedMemorySize, SMEM_BYTES);

    prep_kernel<<<254, 256>>>(lr_w, proj_w, projs_w, sw_w, sw_b, proj_b);
    // branch 0: pairs (2w, 2w+1), x -> o0 (g_mid); proj folded forward
    fused_branch<<<296, 256, SMEM_BYTES>>>(x, lr_b, nullptr, nullptr, 0, 0);
    // branch 1: pairs ((2w+15)&15, 2w); qkv' on o0, projs -> out
    fused_branch<<<296, 256, SMEM_BYTES>>>(nullptr, nullptr, projs_b, out, 1, 15);
}